// round 12
// baseline (speedup 1.0000x reference)
#include <cuda_runtime.h>
#include <cstddef>

// Problem dims (fixed)
#define T_STEPS 128
#define BATCH   2048
#define IN0     18
#define H       256
#define G3      768   // 3*H
#define NBR     14    // real batch rows per block tile (= rows per thread)
#define NBP     16    // padded row stride in smem/xT (keeps 16B alignment)
#define NBLKK   147   // 146 full tiles + 1 overlapping tail tile -> one wave on 148 SMs
#define NTHR    512   // (kh, j): kh = tid>>8 (k-half), j = tid&255

typedef unsigned long long u64;

// ---------------- scratch ----------------
// gate-packed transposed weights: [k][j][4] (r, z, n, pad) -> one LDG.128 per (k,j)
__device__ float4 g_W4_hh0[H * H];   // [k*256 + j]
__device__ float4 g_W4_hh1[H * H];
__device__ float4 g_W4_ih1[H * H];
__device__ float g_xT[(size_t)T_STEPS * NBLKK * IN0 * NBP];  // [t][blk][i][row16]
__device__ float g_h2[BATCH * H];    // layer-1 final hidden, [b][c]

__device__ __forceinline__ int blk_start(int blk) {
    return (blk < NBLKK - 1) ? NBR * blk : (BATCH - NBR);
}

// ---------------- packed fp32x2 helpers ----------------
__device__ __forceinline__ u64 pk2(float a, float b) {
    u64 r; asm("mov.b64 %0, {%1, %2};" : "=l"(r) : "f"(a), "f"(b)); return r;
}
__device__ __forceinline__ void fma2(u64& d, u64 a, u64 b) {
    asm("fma.rn.f32x2 %0, %1, %2, %0;" : "+l"(d) : "l"(a), "l"(b));
}
__device__ __forceinline__ void add2(u64& d, u64 a) {
    asm("add.rn.f32x2 %0, %0, %1;" : "+l"(d) : "l"(a));
}
__device__ __forceinline__ float2 up2(u64 p) {
    float2 f; asm("mov.b64 {%0, %1}, %2;" : "=f"(f.x), "=f"(f.y) : "l"(p)); return f;
}
__device__ __forceinline__ float sigf(float x) {
    return __fdividef(1.f, 1.f + __expf(-x));
}
__device__ __forceinline__ float tanhf_fast(float x) {
    return 2.f * sigf(2.f * x) - 1.f;
}

// ---------------- transpose [3H x H] -> packed [k][j][4] ----------------
__global__ void k_transpose(const float* __restrict__ src, int which) {
    float4* dstv = (which == 0) ? g_W4_hh0 : (which == 1) ? g_W4_hh1 : g_W4_ih1;
    float* dst = (float*)dstv;
    int idx = blockIdx.x * 256 + threadIdx.x;   // grid = 768 blocks -> H*768 threads
    int k = idx / G3;
    int rem = idx - k * G3;
    int g = rem >> 8;          // gate 0..2
    int j = rem & 255;
    dst[(k * 256 + j) * 4 + g] = src[(g * H + j) * H + k];
    if (g == 0) dst[(k * 256 + j) * 4 + 3] = 0.f;   // pad
}

// ---------------- pre-transpose x: [t][b][i] -> [t][blk][i][row16] ----------------
__global__ void k_xt(const float* __restrict__ x) {
    size_t idx = (size_t)blockIdx.x * 256 + threadIdx.x;
    const size_t total = (size_t)T_STEPS * NBLKK * IN0 * NBR;
    if (idx >= total) return;
    int row = (int)(idx % NBR);
    size_t r1 = idx / NBR;
    int i = (int)(r1 % IN0);
    size_t r2 = r1 / IN0;
    int blk = (int)(r2 % NBLKK);
    int t = (int)(r2 / NBLKK);
    int b = blk_start(blk) + row;
    g_xT[(((size_t)t * NBLKK + blk) * IN0 + i) * NBP + row] =
        x[((size_t)t * BATCH + b) * IN0 + i];
}

// load one 14-wide padded row (7 u64) from ptr (16B-aligned, stride NBP floats)
#define LOAD_ROW(ptr, b0, b1, b2, b3v)                                       \
    ulonglong2 b0, b1, b2; u64 b3v;                                          \
    do {                                                                     \
        const ulonglong2* _hp = (const ulonglong2*)(ptr);                    \
        b0 = _hp[0]; b1 = _hp[1]; b2 = _hp[2];                               \
        b3v = ((const u64*)(ptr))[6];                                        \
    } while (0)

// fma a 14-batch row (7 u64) against one gate weight into 7 accumulators
#define ROW_FMA(acc, wv, b0, b1, b2, b3v)                                    \
    do {                                                                     \
        fma2(acc[0], b0.x, wv); fma2(acc[1], b0.y, wv);                      \
        fma2(acc[2], b1.x, wv); fma2(acc[3], b1.y, wv);                      \
        fma2(acc[4], b2.x, wv); fma2(acc[5], b2.y, wv);                      \
        fma2(acc[6], b3v, wv);                                               \
    } while (0)

// ---- partial single-matrix gemm over 128 k's starting at k0, chunk=4 ----
__device__ __forceinline__ void gemm_part1(const float4* __restrict__ W4,
                                           const float* __restrict__ sbuf,
                                           u64* __restrict__ ar, u64* __restrict__ az,
                                           u64* __restrict__ an, int j, int k0) {
    const float4* wp = W4 + (k0 << 8) + j;   // stride per k = 256 float4
    const float* hb = sbuf + k0 * NBP;
    float4 wb[2][4];
#pragma unroll
    for (int kk = 0; kk < 4; kk++) wb[0][kk] = __ldg(wp + kk * 256);
#pragma unroll 2
    for (int c = 0; c < 32; c++) {
        const int cur = c & 1, nxt = cur ^ 1;
        if (c + 1 < 32) {
#pragma unroll
            for (int kk = 0; kk < 4; kk++)
                wb[nxt][kk] = __ldg(wp + ((c + 1) * 4 + kk) * 256);
        }
#pragma unroll
        for (int kk = 0; kk < 4; kk++) {
            const int k = c * 4 + kk;
            float4 w = wb[cur][kk];
            u64 wr2 = pk2(w.x, w.x), wz2 = pk2(w.y, w.y), wn2 = pk2(w.z, w.z);
            LOAD_ROW(hb + k * NBP, b0, b1, b2, b3v);
            ROW_FMA(ar, wr2, b0, b1, b2, b3v);
            ROW_FMA(az, wz2, b0, b1, b2, b3v);
            ROW_FMA(an, wn2, b0, b1, b2, b3v);
        }
    }
}

// ---- partial dual gemm (layer 1) over 128 k's starting at k0, chunk=2 ----
__device__ __forceinline__ void gemm_part2(const float4* __restrict__ W4i,
                                           const float4* __restrict__ W4h,
                                           const float* __restrict__ sxb,
                                           const float* __restrict__ shb,
                                           u64* __restrict__ ar, u64* __restrict__ az,
                                           u64* __restrict__ axn, u64* __restrict__ ahn,
                                           int j, int k0) {
    const float4* wpi = W4i + (k0 << 8) + j;
    const float4* wph = W4h + (k0 << 8) + j;
    const float* xb = sxb + k0 * NBP;
    const float* hb = shb + k0 * NBP;
    float4 wb[2][2][2];   // [buf][kk][matrix: 0=input 1=hidden]
#pragma unroll
    for (int kk = 0; kk < 2; kk++) {
        wb[0][kk][0] = __ldg(wpi + kk * 256);
        wb[0][kk][1] = __ldg(wph + kk * 256);
    }
#pragma unroll 2
    for (int c = 0; c < 64; c++) {
        const int cur = c & 1, nxt = cur ^ 1;
        if (c + 1 < 64) {
#pragma unroll
            for (int kk = 0; kk < 2; kk++) {
                wb[nxt][kk][0] = __ldg(wpi + ((c + 1) * 2 + kk) * 256);
                wb[nxt][kk][1] = __ldg(wph + ((c + 1) * 2 + kk) * 256);
            }
        }
#pragma unroll
        for (int kk = 0; kk < 2; kk++) {
            const int k = c * 2 + kk;
            float4 wi = wb[cur][kk][0];
            float4 wh = wb[cur][kk][1];
            {
                u64 wr2 = pk2(wi.x, wi.x), wz2 = pk2(wi.y, wi.y), wn2 = pk2(wi.z, wi.z);
                LOAD_ROW(xb + k * NBP, b0, b1, b2, b3v);
                ROW_FMA(ar, wr2, b0, b1, b2, b3v);
                ROW_FMA(az, wz2, b0, b1, b2, b3v);
                ROW_FMA(axn, wn2, b0, b1, b2, b3v);
            }
            {
                u64 wr2 = pk2(wh.x, wh.x), wz2 = pk2(wh.y, wh.y), wn2 = pk2(wh.z, wh.z);
                LOAD_ROW(hb + k * NBP, b0, b1, b2, b3v);
                ROW_FMA(ar, wr2, b0, b1, b2, b3v);
                ROW_FMA(az, wz2, b0, b1, b2, b3v);
                ROW_FMA(ahn, wn2, b0, b1, b2, b3v);
            }
        }
    }
}

// ---- partial-sum exchange: kh1 stores 28 u64 as 14 ulonglong2, kh0 adds ----
// layout red[p*256 + j] -> lanes consecutive, conflict-free
__device__ __forceinline__ void red_store(ulonglong2* red, int j,
                                          const u64* ar, const u64* az,
                                          const u64* axn, const u64* ahn) {
    red[0 * 256 + j]  = make_ulonglong2(ar[0], ar[1]);
    red[1 * 256 + j]  = make_ulonglong2(ar[2], ar[3]);
    red[2 * 256 + j]  = make_ulonglong2(ar[4], ar[5]);
    red[3 * 256 + j]  = make_ulonglong2(ar[6], az[0]);
    red[4 * 256 + j]  = make_ulonglong2(az[1], az[2]);
    red[5 * 256 + j]  = make_ulonglong2(az[3], az[4]);
    red[6 * 256 + j]  = make_ulonglong2(az[5], az[6]);
    red[7 * 256 + j]  = make_ulonglong2(axn[0], axn[1]);
    red[8 * 256 + j]  = make_ulonglong2(axn[2], axn[3]);
    red[9 * 256 + j]  = make_ulonglong2(axn[4], axn[5]);
    red[10 * 256 + j] = make_ulonglong2(axn[6], ahn[0]);
    red[11 * 256 + j] = make_ulonglong2(ahn[1], ahn[2]);
    red[12 * 256 + j] = make_ulonglong2(ahn[3], ahn[4]);
    red[13 * 256 + j] = make_ulonglong2(ahn[5], ahn[6]);
}

__device__ __forceinline__ void red_add(const ulonglong2* red, int j,
                                        u64* ar, u64* az, u64* axn, u64* ahn) {
    ulonglong2 v;
    v = red[0 * 256 + j];  add2(ar[0], v.x);  add2(ar[1], v.y);
    v = red[1 * 256 + j];  add2(ar[2], v.x);  add2(ar[3], v.y);
    v = red[2 * 256 + j];  add2(ar[4], v.x);  add2(ar[5], v.y);
    v = red[3 * 256 + j];  add2(ar[6], v.x);  add2(az[0], v.y);
    v = red[4 * 256 + j];  add2(az[1], v.x);  add2(az[2], v.y);
    v = red[5 * 256 + j];  add2(az[3], v.x);  add2(az[4], v.y);
    v = red[6 * 256 + j];  add2(az[5], v.x);  add2(az[6], v.y);
    v = red[7 * 256 + j];  add2(axn[0], v.x); add2(axn[1], v.y);
    v = red[8 * 256 + j];  add2(axn[2], v.x); add2(axn[3], v.y);
    v = red[9 * 256 + j];  add2(axn[4], v.x); add2(axn[5], v.y);
    v = red[10 * 256 + j]; add2(axn[6], v.x); add2(ahn[0], v.y);
    v = red[11 * 256 + j]; add2(ahn[1], v.x); add2(ahn[2], v.y);
    v = red[12 * 256 + j]; add2(ahn[3], v.x); add2(ahn[4], v.y);
    v = red[13 * 256 + j]; add2(ahn[5], v.x); add2(ahn[6], v.y);
}

// gates -> hnew[14]; old h read from smem slice (thread-private)
__device__ __forceinline__ void epilogue(u64* ar, u64* az, u64* axn, u64* ahn,
                                         const float* hold, float* hnew) {
#pragma unroll
    for (int p = 0; p < 7; p++) {
        float2 r2 = up2(ar[p]), z2 = up2(az[p]), x2 = up2(axn[p]), h2 = up2(ahn[p]);
        float r0 = sigf(r2.x), z0 = sigf(z2.x);
        float n0 = tanhf_fast(x2.x + r0 * h2.x);
        hnew[2 * p] = n0 + z0 * (hold[2 * p] - n0);
        float r1 = sigf(r2.y), z1 = sigf(z2.y);
        float n1 = tanhf_fast(x2.y + r1 * h2.y);
        hnew[2 * p + 1] = n1 + z1 * (hold[2 * p + 1] - n1);
    }
}

// write hnew[14] to a padded row (3x float4 + 1x float2)
__device__ __forceinline__ void store_row(float* dst, const float* hnew) {
    float4* w4 = (float4*)dst;
    w4[0] = make_float4(hnew[0], hnew[1], hnew[2], hnew[3]);
    w4[1] = make_float4(hnew[4], hnew[5], hnew[6], hnew[7]);
    w4[2] = make_float4(hnew[8], hnew[9], hnew[10], hnew[11]);
    ((float2*)(dst + 12))[0] = make_float2(hnew[12], hnew[13]);
}

// ---------------- fused 2-layer GRU, k-split across two 256-thread halves ----------------
__global__ __launch_bounds__(NTHR, 1)
void k_gru(const float* __restrict__ Wih0,
           const float* __restrict__ bih0, const float* __restrict__ bhh0,
           const float* __restrict__ bih1, const float* __restrict__ bhh1) {
    extern __shared__ float smem[];
    float* sWih = smem;                       // [i][g], 18*768 = 13824 floats
    float* sh0  = sWih + IN0 * G3;            // layer-0 h, 2 bufs x [c][row16] (4096 each)
    float* sh1  = sh0 + 2 * H * NBP;          // layer-1 h, 2 bufs
    float* sx   = sh1 + 2 * H * NBP;          // x tile, 2 bufs x [i][row16]
    ulonglong2* red = (ulonglong2*)(sx + 2 * IN0 * NBP);  // 14*256 ulonglong2 = 56KB

    const int tid = threadIdx.x;
    const int kh  = tid >> 8;        // k-half
    const int j   = tid & 255;
    const int k0  = kh << 7;         // 0 or 128
    const int bbase = blk_start(blockIdx.x);
    const size_t xtile = (size_t)IN0 * NBP;

    for (int idx = tid; idx < IN0 * G3; idx += NTHR) {
        int i = idx / G3, g = idx - i * G3;
        sWih[idx] = Wih0[g * IN0 + i];
    }
    // zero buffer 0 of both states
    for (int idx = tid; idx < H * NBP; idx += NTHR) {
        sh0[idx] = 0.f;
        sh1[idx] = 0.f;
    }
    // stage x[0] into sx buffer 0
    {
        const float4* src = (const float4*)(g_xT + ((size_t)0 * NBLKK + blockIdx.x) * xtile);
        float4* dst = (float4*)sx;
        for (int idx = tid; idx < IN0 * NBP / 4; idx += NTHR) dst[idx] = src[idx];
    }

    // biases folded into accumulator init; only kh==0 carries them (kh==1 adds partials)
    const float brz0 = (kh == 0) ? (bih0[j] + bhh0[j]) : 0.f;
    const float bzz0 = (kh == 0) ? (bih0[H + j] + bhh0[H + j]) : 0.f;
    const float bxn0 = (kh == 0) ? bih0[2 * H + j] : 0.f;
    const float bhn0 = (kh == 0) ? bhh0[2 * H + j] : 0.f;
    const float brz1 = (kh == 0) ? (bih1[j] + bhh1[j]) : 0.f;
    const float bzz1 = (kh == 0) ? (bih1[H + j] + bhh1[H + j]) : 0.f;
    const float bxn1 = (kh == 0) ? bih1[2 * H + j] : 0.f;
    const float bhn1 = (kh == 0) ? bhh1[2 * H + j] : 0.f;
    __syncthreads();

    for (int t = 0; t < T_STEPS; t++) {
        const int tc = t & 1, tn = tc ^ 1;
        const float* sh0c = sh0 + tc * (H * NBP);
        float*       sh0n = sh0 + tn * (H * NBP);
        const float* sh1c = sh1 + tc * (H * NBP);
        float*       sh1n = sh1 + tn * (H * NBP);
        const float* sxc  = sx + tc * (IN0 * NBP);

        // ---------- layer 0 (partial over this thread's k-half) ----------
        u64 ar[7], az[7], axn[7], ahn[7];
#pragma unroll
        for (int p = 0; p < 7; p++) {
            ar[p] = pk2(brz0, brz0); az[p] = pk2(bzz0, bzz0);
            axn[p] = pk2(bxn0, bxn0); ahn[p] = pk2(bhn0, bhn0);
        }
        // input projection split: kh0 -> i 0..8, kh1 -> i 9..17
        {
            const int i0 = kh * 9;
#pragma unroll
            for (int ii = 0; ii < 9; ii++) {
                const int i = i0 + ii;
                float wr = sWih[i * G3 + j];
                float wz = sWih[i * G3 + H + j];
                float wn = sWih[i * G3 + 2 * H + j];
                u64 wr2 = pk2(wr, wr), wz2 = pk2(wz, wz), wn2 = pk2(wn, wn);
                LOAD_ROW(sxc + i * NBP, b0, b1, b2, b3v);
                ROW_FMA(ar, wr2, b0, b1, b2, b3v);
                ROW_FMA(az, wz2, b0, b1, b2, b3v);
                ROW_FMA(axn, wn2, b0, b1, b2, b3v);
            }
        }
        gemm_part1(g_W4_hh0, sh0c, ar, az, ahn, j, k0);
        if (kh) red_store(red, j, ar, az, axn, ahn);
        __syncthreads();   // A0: partials visible; all reads of sh0c done

        if (!kh) {
            red_add(red, j, ar, az, axn, ahn);
            float hnew[NBR];
            epilogue(ar, az, axn, ahn, sh0c + j * NBP, hnew);
            store_row(sh0n + j * NBP, hnew);
        } else if (t + 1 < T_STEPS) {
            // overlap: stage x[t+1] into the other sx buffer
            const float4* src =
                (const float4*)(g_xT + ((size_t)(t + 1) * NBLKK + blockIdx.x) * xtile);
            float4* dst = (float4*)(sx + tn * (IN0 * NBP));
            for (int idx = j; idx < IN0 * NBP / 4; idx += 256) dst[idx] = src[idx];
        }
        __syncthreads();   // B0: sh0n + sx[tn] visible

        // ---------- layer 1 (input = NEW h0; partial over k-half) ----------
#pragma unroll
        for (int p = 0; p < 7; p++) {
            ar[p] = pk2(brz1, brz1); az[p] = pk2(bzz1, bzz1);
            axn[p] = pk2(bxn1, bxn1); ahn[p] = pk2(bhn1, bhn1);
        }
        gemm_part2(g_W4_ih1, g_W4_hh1, sh0n, sh1c, ar, az, axn, ahn, j, k0);
        if (kh) red_store(red, j, ar, az, axn, ahn);
        __syncthreads();   // A1: partials visible; all reads of sh1c done

        if (!kh) {
            red_add(red, j, ar, az, axn, ahn);
            float hnew[NBR];
            epilogue(ar, az, axn, ahn, sh1c + j * NBP, hnew);
            store_row(sh1n + j * NBP, hnew);
            if (t == T_STEPS - 1) {
#pragma unroll
                for (int b = 0; b < NBR; b++)
                    g_h2[(size_t)(bbase + b) * H + j] = hnew[b];
            }
        }
        __syncthreads();   // B1: sh1n visible before next step
    }
}

// ---------------- FC head ----------------
__global__ void k_fc(const float* __restrict__ fcw, const float* __restrict__ fcb,
                     float* __restrict__ out) {
    int warp = threadIdx.x >> 5, lane = threadIdx.x & 31;
    int row = blockIdx.x * 8 + warp;
    const float* h = &g_h2[(size_t)row * H];
    float a0 = 0.f, a1 = 0.f, a2 = 0.f, a3 = 0.f;
    for (int k = lane; k < H; k += 32) {
        float hv = h[k];
        a0 += hv * fcw[k];
        a1 += hv * fcw[H + k];
        a2 += hv * fcw[2 * H + k];
        a3 += hv * fcw[3 * H + k];
    }
#pragma unroll
    for (int off = 16; off; off >>= 1) {
        a0 += __shfl_xor_sync(0xffffffffu, a0, off);
        a1 += __shfl_xor_sync(0xffffffffu, a1, off);
        a2 += __shfl_xor_sync(0xffffffffu, a2, off);
        a3 += __shfl_xor_sync(0xffffffffu, a3, off);
    }
    if (lane == 0) {
        float l0 = a0 + fcb[0], l1 = a1 + fcb[1], l2 = a2 + fcb[2], l3 = a3 + fcb[3];
        out[row * 4 + 0] = 2.f / (1.f + expf(-l0)) - 1.f;
        out[row * 4 + 1] = 2.f / (1.f + expf(-l1)) - 1.f;
        out[row * 4 + 2] = 2.f / (1.f + expf(-l2)) - 1.f;
        out[row * 4 + 3] = 2.f / (1.f + expf(-l3)) - 1.f;
    }
}

extern "C" void kernel_launch(void* const* d_in, const int* in_sizes, int n_in,
                              void* d_out, int out_size) {
    const float* x    = (const float*)d_in[0];
    const float* Wih0 = (const float*)d_in[1];
    const float* Whh0 = (const float*)d_in[2];
    const float* bih0 = (const float*)d_in[3];
    const float* bhh0 = (const float*)d_in[4];
    const float* Wih1 = (const float*)d_in[5];
    const float* Whh1 = (const float*)d_in[6];
    const float* bih1 = (const float*)d_in[7];
    const float* bhh1 = (const float*)d_in[8];
    const float* fcw  = (const float*)d_in[9];
    const float* fcb  = (const float*)d_in[10];
    float* out = (float*)d_out;

    // floats: sWih 13824 + sh0 8192 + sh1 8192 + sx 576 = 30784 -> 123136 B
    // + red 14*256*16 = 57344 B  => 180480 B total
    const int gru_smem =
        (IN0 * G3 + 4 * H * NBP + 2 * IN0 * NBP) * (int)sizeof(float) + 14 * 256 * 16;
    static int smem_set = 0;
    if (!smem_set) {
        cudaFuncSetAttribute(k_gru, cudaFuncAttributeMaxDynamicSharedMemorySize, gru_smem);
        smem_set = 1;
    }

    {
        const size_t total = (size_t)T_STEPS * NBLKK * IN0 * NBR;
        k_xt<<<(int)((total + 255) / 256), 256>>>(x);
    }
    k_transpose<<<G3, 256>>>(Whh0, 0);
    k_transpose<<<G3, 256>>>(Whh1, 1);
    k_transpose<<<G3, 256>>>(Wih1, 2);
    k_gru<<<NBLKK, NTHR, gru_smem>>>(Wih0, bih0, bhh0, bih1, bhh1);
    k_fc<<<BATCH / 8, 256>>>(fcw, fcb, out);
}

// round 13
// speedup vs baseline: 1.1158x; 1.1158x over previous
#include <cuda_runtime.h>
#include <cstddef>

// Problem dims (fixed)
#define T_STEPS 128
#define BATCH   2048
#define IN0     18
#define H       256
#define G3      768   // 3*H
#define NBR     14    // real batch rows per block tile (= rows per thread)
#define NBP     16    // padded row stride in smem/xT (keeps 16B alignment)
#define NBLKK   147   // 146 full tiles + 1 overlapping tail tile -> one wave on 148 SMs
#define NTHR    256   // one thread per hidden unit j

typedef unsigned long long u64;

// ---------------- scratch ----------------
// gate-packed transposed weights: [k][j][4] (r, z, n, pad) -> one LDG.128 per (k,j)
__device__ float4 g_W4_hh0[H * H];   // [k*256 + j]
__device__ float4 g_W4_hh1[H * H];
__device__ float4 g_W4_ih1[H * H];
__device__ float g_xT[(size_t)T_STEPS * NBLKK * IN0 * NBP];  // [t][blk][i][row16]
__device__ float g_h2[BATCH * H];    // layer-1 final hidden, [b][c]

__device__ __forceinline__ int blk_start(int blk) {
    return (blk < NBLKK - 1) ? NBR * blk : (BATCH - NBR);
}

// ---------------- packed fp32x2 helpers ----------------
__device__ __forceinline__ u64 pk2(float a, float b) {
    u64 r; asm("mov.b64 %0, {%1, %2};" : "=l"(r) : "f"(a), "f"(b)); return r;
}
__device__ __forceinline__ void fma2(u64& d, u64 a, u64 b) {
    asm("fma.rn.f32x2 %0, %1, %2, %0;" : "+l"(d) : "l"(a), "l"(b));
}
__device__ __forceinline__ float2 up2(u64 p) {
    float2 f; asm("mov.b64 {%0, %1}, %2;" : "=f"(f.x), "=f"(f.y) : "l"(p)); return f;
}
__device__ __forceinline__ float sigf(float x) {
    return __fdividef(1.f, 1.f + __expf(-x));
}
__device__ __forceinline__ float tanhf_fast(float x) {
    return 2.f * sigf(2.f * x) - 1.f;
}

// ---------------- transpose [3H x H] -> packed [k][j][4] ----------------
__global__ void k_transpose(const float* __restrict__ src, int which) {
    float4* dstv = (which == 0) ? g_W4_hh0 : (which == 1) ? g_W4_hh1 : g_W4_ih1;
    float* dst = (float*)dstv;
    int idx = blockIdx.x * 256 + threadIdx.x;   // grid = 768 blocks -> H*768 threads
    int k = idx / G3;
    int rem = idx - k * G3;
    int g = rem >> 8;          // gate 0..2
    int j = rem & 255;
    dst[(k * 256 + j) * 4 + g] = src[(g * H + j) * H + k];
    if (g == 0) dst[(k * 256 + j) * 4 + 3] = 0.f;   // pad
}

// ---------------- pre-transpose x: [t][b][i] -> [t][blk][i][row16] ----------------
__global__ void k_xt(const float* __restrict__ x) {
    size_t idx = (size_t)blockIdx.x * 256 + threadIdx.x;
    const size_t total = (size_t)T_STEPS * NBLKK * IN0 * NBR;
    if (idx >= total) return;
    int row = (int)(idx % NBR);
    size_t r1 = idx / NBR;
    int i = (int)(r1 % IN0);
    size_t r2 = r1 / IN0;
    int blk = (int)(r2 % NBLKK);
    int t = (int)(r2 / NBLKK);
    int b = blk_start(blk) + row;
    g_xT[(((size_t)t * NBLKK + blk) * IN0 + i) * NBP + row] =
        x[((size_t)t * BATCH + b) * IN0 + i];
}

// load one 14-wide padded row (7 u64) from ptr (16B-aligned, stride NBP floats)
#define LOAD_ROW(ptr, b0, b1, b2, b3v)                                       \
    ulonglong2 b0, b1, b2; u64 b3v;                                          \
    do {                                                                     \
        const ulonglong2* _hp = (const ulonglong2*)(ptr);                    \
        b0 = _hp[0]; b1 = _hp[1]; b2 = _hp[2];                               \
        b3v = ((const u64*)(ptr))[6];                                        \
    } while (0)

// fma a 14-batch row (7 u64) against one gate weight into 7 accumulators
#define ROW_FMA(acc, wv, b0, b1, b2, b3v)                                    \
    do {                                                                     \
        fma2(acc[0], b0.x, wv); fma2(acc[1], b0.y, wv);                      \
        fma2(acc[2], b1.x, wv); fma2(acc[3], b1.y, wv);                      \
        fma2(acc[4], b2.x, wv); fma2(acc[5], b2.y, wv);                      \
        fma2(acc[6], b3v, wv);                                               \
    } while (0)

// ---- fused triple-matrix gemm: L1(t) [Wih1*h0 + Whh1*h1] and L0(t+1) [Whh0*h0] ----
// h0 row is loaded once and shared by Wih1 and Whh0 sides. chunk=2 double buffer.
__device__ __forceinline__ void gemm_tri(const float* __restrict__ sh0row,
                                         const float* __restrict__ sh1row,
                                         u64* __restrict__ a1r, u64* __restrict__ a1z,
                                         u64* __restrict__ a1xn, u64* __restrict__ a1hn,
                                         u64* __restrict__ a0r, u64* __restrict__ a0z,
                                         u64* __restrict__ a0hn, int j) {
    const float4* pi1 = g_W4_ih1 + j;
    const float4* ph1 = g_W4_hh1 + j;
    const float4* ph0 = g_W4_hh0 + j;
    float4 wb[2][2][3];   // [buf][kk][matrix]
#pragma unroll
    for (int kk = 0; kk < 2; kk++) {
        wb[0][kk][0] = __ldg(pi1 + kk * 256);
        wb[0][kk][1] = __ldg(ph1 + kk * 256);
        wb[0][kk][2] = __ldg(ph0 + kk * 256);
    }
#pragma unroll 2
    for (int c = 0; c < H / 2; c++) {
        const int cur = c & 1, nxt = cur ^ 1;
        if (c + 1 < H / 2) {
#pragma unroll
            for (int kk = 0; kk < 2; kk++) {
                wb[nxt][kk][0] = __ldg(pi1 + ((c + 1) * 2 + kk) * 256);
                wb[nxt][kk][1] = __ldg(ph1 + ((c + 1) * 2 + kk) * 256);
                wb[nxt][kk][2] = __ldg(ph0 + ((c + 1) * 2 + kk) * 256);
            }
        }
#pragma unroll
        for (int kk = 0; kk < 2; kk++) {
            const int k = c * 2 + kk;
            float4 wi1 = wb[cur][kk][0];
            float4 wh1 = wb[cur][kk][1];
            float4 wh0 = wb[cur][kk][2];
            // h0 row: feeds L1 input-side AND L0 hidden-side
            {
                LOAD_ROW(sh0row + k * NBP, b0, b1, b2, b3v);
                u64 w1 = pk2(wi1.x, wi1.x), w2 = pk2(wi1.y, wi1.y), w3 = pk2(wi1.z, wi1.z);
                ROW_FMA(a1r, w1, b0, b1, b2, b3v);
                ROW_FMA(a1z, w2, b0, b1, b2, b3v);
                ROW_FMA(a1xn, w3, b0, b1, b2, b3v);
                u64 w4 = pk2(wh0.x, wh0.x), w5 = pk2(wh0.y, wh0.y), w6 = pk2(wh0.z, wh0.z);
                ROW_FMA(a0r, w4, b0, b1, b2, b3v);
                ROW_FMA(a0z, w5, b0, b1, b2, b3v);
                ROW_FMA(a0hn, w6, b0, b1, b2, b3v);
            }
            // h1 row: L1 hidden-side
            {
                LOAD_ROW(sh1row + k * NBP, b0, b1, b2, b3v);
                u64 w1 = pk2(wh1.x, wh1.x), w2 = pk2(wh1.y, wh1.y), w3 = pk2(wh1.z, wh1.z);
                ROW_FMA(a1r, w1, b0, b1, b2, b3v);
                ROW_FMA(a1z, w2, b0, b1, b2, b3v);
                ROW_FMA(a1hn, w3, b0, b1, b2, b3v);
            }
        }
    }
}

// gates -> hnew[14]; old h read from smem slice (thread-private)
__device__ __forceinline__ void epilogue(u64* ar, u64* az, u64* axn, u64* ahn,
                                         const float* hold, float* hnew) {
#pragma unroll
    for (int p = 0; p < 7; p++) {
        float2 r2 = up2(ar[p]), z2 = up2(az[p]), x2 = up2(axn[p]), h2 = up2(ahn[p]);
        float r0 = sigf(r2.x), z0 = sigf(z2.x);
        float n0 = tanhf_fast(x2.x + r0 * h2.x);
        hnew[2 * p] = n0 + z0 * (hold[2 * p] - n0);
        float r1 = sigf(r2.y), z1 = sigf(z2.y);
        float n1 = tanhf_fast(x2.y + r1 * h2.y);
        hnew[2 * p + 1] = n1 + z1 * (hold[2 * p + 1] - n1);
    }
}

// write hnew[14] to a padded row (3x float4 + 1x float2)
__device__ __forceinline__ void store_row(float* dst, const float* hnew) {
    float4* w4 = (float4*)dst;
    w4[0] = make_float4(hnew[0], hnew[1], hnew[2], hnew[3]);
    w4[1] = make_float4(hnew[4], hnew[5], hnew[6], hnew[7]);
    w4[2] = make_float4(hnew[8], hnew[9], hnew[10], hnew[11]);
    ((float2*)(dst + 12))[0] = make_float2(hnew[12], hnew[13]);
}

// ---------------- fused 2-layer GRU, layer-pipelined: ONE phase + ONE barrier per step ----------------
// Phase p computes L1(p) [h1(p) from h0(p), h1(p-1)] AND L0(p+1) [h0(p+1) from h0(p), x(p+1)].
__global__ __launch_bounds__(NTHR, 1)
void k_gru(const float* __restrict__ Wih0,
           const float* __restrict__ bih0, const float* __restrict__ bhh0,
           const float* __restrict__ bih1, const float* __restrict__ bhh1) {
    extern __shared__ float smem[];
    float* sWih = smem;                       // [i][g], 18*768 = 13824
    float* sh0  = sWih + IN0 * G3;            // layer-0 h, 2 bufs x [c][row16]
    float* sh1  = sh0 + 2 * H * NBP;          // layer-1 h, 2 bufs
    float* sx   = sh1 + 2 * H * NBP;          // x tile, 2 bufs x [i][row16]

    const int j = threadIdx.x;
    const int bbase = blk_start(blockIdx.x);
    const size_t xtile = (size_t)IN0 * NBP;

    for (int idx = j; idx < IN0 * G3; idx += NTHR) {
        int i = idx / G3, g = idx - i * G3;
        sWih[idx] = Wih0[g * IN0 + i];
    }
    // zero buffer 0 of both states (phase 0 reads buf 0)
    for (int idx = j; idx < H * NBP; idx += NTHR) {
        sh0[idx] = 0.f;
        sh1[idx] = 0.f;
    }
    // stage x(0) into sx[1] (prologue input) and x(1) into sx[0] (phase-0 input)
    {
        const float4* s0 = (const float4*)(g_xT + ((size_t)0 * NBLKK + blockIdx.x) * xtile);
        const float4* s1 = (const float4*)(g_xT + ((size_t)1 * NBLKK + blockIdx.x) * xtile);
        float4* d1 = (float4*)(sx + IN0 * NBP);
        float4* d0 = (float4*)sx;
        for (int idx = j; idx < IN0 * NBP / 4; idx += NTHR) {
            d1[idx] = s0[idx];
            d0[idx] = s1[idx];
        }
    }

    const float brz0 = bih0[j] + bhh0[j];
    const float bzz0 = bih0[H + j] + bhh0[H + j];
    const float bxn0 = bih0[2 * H + j];
    const float bhn0 = bhh0[2 * H + j];
    const float brz1 = bih1[j] + bhh1[j];
    const float bzz1 = bih1[H + j] + bhh1[H + j];
    const float bxn1 = bih1[2 * H + j];
    const float bhn1 = bhh1[2 * H + j];
    __syncthreads();

    // input projection K=18 from sxbuf into (ar, az, axn)
#define INPUT_PROJ(sxbuf, ar, az, axn)                                        \
    do {                                                                      \
        _Pragma("unroll")                                                     \
        for (int i = 0; i < IN0; i++) {                                       \
            float wr = sWih[i * G3 + j];                                      \
            float wz = sWih[i * G3 + H + j];                                  \
            float wn = sWih[i * G3 + 2 * H + j];                              \
            u64 wr2 = pk2(wr, wr), wz2 = pk2(wz, wz), wn2 = pk2(wn, wn);      \
            LOAD_ROW((sxbuf) + i * NBP, b0, b1, b2, b3v);                     \
            ROW_FMA(ar, wr2, b0, b1, b2, b3v);                                \
            ROW_FMA(az, wz2, b0, b1, b2, b3v);                                \
            ROW_FMA(axn, wn2, b0, b1, b2, b3v);                               \
        }                                                                     \
    } while (0)

    // ---------- prologue: h0(0) from x(0) (hidden state is zero) ----------
    {
        u64 a0r[7], a0z[7], a0xn[7], a0hn[7];
#pragma unroll
        for (int p = 0; p < 7; p++) {
            a0r[p] = pk2(brz0, brz0); a0z[p] = pk2(bzz0, bzz0);
            a0xn[p] = pk2(bxn0, bxn0); a0hn[p] = pk2(bhn0, bhn0);
        }
        INPUT_PROJ(sx + IN0 * NBP, a0r, a0z, a0xn);
        float hnew[NBR];
        float hzero[NBR];
#pragma unroll
        for (int b = 0; b < NBR; b++) hzero[b] = 0.f;
        epilogue(a0r, a0z, a0xn, a0hn, hzero, hnew);
        store_row(sh0 + j * NBP, hnew);   // h0(0) -> buf 0
    }
    __syncthreads();

    // ---------- main: 128 phases, one barrier each ----------
    for (int p = 0; p < T_STEPS; p++) {
        const int tc = p & 1, tn = tc ^ 1;
        const float* sh0c = sh0 + tc * (H * NBP);   // h0(p)
        float*       sh0n = sh0 + tn * (H * NBP);
        const float* sh1c = sh1 + tc * (H * NBP);   // h1(p-1)
        float*       sh1n = sh1 + tn * (H * NBP);
        const float* sxc  = sx + tc * (IN0 * NBP);  // x(p+1)

        u64 a1r[7], a1z[7], a1xn[7], a1hn[7];
        u64 a0r[7], a0z[7], a0xn[7], a0hn[7];
#pragma unroll
        for (int q = 0; q < 7; q++) {
            a1r[q] = pk2(brz1, brz1); a1z[q] = pk2(bzz1, bzz1);
            a1xn[q] = pk2(bxn1, bxn1); a1hn[q] = pk2(bhn1, bhn1);
            a0r[q] = pk2(brz0, brz0); a0z[q] = pk2(bzz0, bzz0);
            a0xn[q] = pk2(bxn0, bxn0); a0hn[q] = pk2(bhn0, bhn0);
        }

        INPUT_PROJ(sxc, a0r, a0z, a0xn);                      // L0(p+1) input part
        gemm_tri(sh0c, sh1c, a1r, a1z, a1xn, a1hn, a0r, a0z, a0hn, j);

        // stage x(p+2) into the other sx buffer
        if (p + 2 < T_STEPS) {
            const float4* src =
                (const float4*)(g_xT + ((size_t)(p + 2) * NBLKK + blockIdx.x) * xtile);
            float4* dst = (float4*)(sx + tn * (IN0 * NBP));
            for (int idx = j; idx < IN0 * NBP / 4; idx += NTHR) dst[idx] = src[idx];
        }

        // epilogue L1(p): h1(p) from h1(p-1)
        {
            float hnew[NBR];
            epilogue(a1r, a1z, a1xn, a1hn, sh1c + j * NBP, hnew);
            store_row(sh1n + j * NBP, hnew);
            if (p == T_STEPS - 1) {
#pragma unroll
                for (int b = 0; b < NBR; b++)
                    g_h2[(size_t)(bbase + b) * H + j] = hnew[b];
            }
        }
        // epilogue L0(p+1): h0(p+1) from h0(p)  (p=127: dead value, never read)
        {
            float hnew[NBR];
            epilogue(a0r, a0z, a0xn, a0hn, sh0c + j * NBP, hnew);
            store_row(sh0n + j * NBP, hnew);
        }
        __syncthreads();   // phase results visible
    }
#undef INPUT_PROJ
}

// ---------------- FC head ----------------
__global__ void k_fc(const float* __restrict__ fcw, const float* __restrict__ fcb,
                     float* __restrict__ out) {
    int warp = threadIdx.x >> 5, lane = threadIdx.x & 31;
    int row = blockIdx.x * 8 + warp;
    const float* h = &g_h2[(size_t)row * H];
    float a0 = 0.f, a1 = 0.f, a2 = 0.f, a3 = 0.f;
    for (int k = lane; k < H; k += 32) {
        float hv = h[k];
        a0 += hv * fcw[k];
        a1 += hv * fcw[H + k];
        a2 += hv * fcw[2 * H + k];
        a3 += hv * fcw[3 * H + k];
    }
#pragma unroll
    for (int off = 16; off; off >>= 1) {
        a0 += __shfl_xor_sync(0xffffffffu, a0, off);
        a1 += __shfl_xor_sync(0xffffffffu, a1, off);
        a2 += __shfl_xor_sync(0xffffffffu, a2, off);
        a3 += __shfl_xor_sync(0xffffffffu, a3, off);
    }
    if (lane == 0) {
        float l0 = a0 + fcb[0], l1 = a1 + fcb[1], l2 = a2 + fcb[2], l3 = a3 + fcb[3];
        out[row * 4 + 0] = 2.f / (1.f + expf(-l0)) - 1.f;
        out[row * 4 + 1] = 2.f / (1.f + expf(-l1)) - 1.f;
        out[row * 4 + 2] = 2.f / (1.f + expf(-l2)) - 1.f;
        out[row * 4 + 3] = 2.f / (1.f + expf(-l3)) - 1.f;
    }
}

extern "C" void kernel_launch(void* const* d_in, const int* in_sizes, int n_in,
                              void* d_out, int out_size) {
    const float* x    = (const float*)d_in[0];
    const float* Wih0 = (const float*)d_in[1];
    const float* Whh0 = (const float*)d_in[2];
    const float* bih0 = (const float*)d_in[3];
    const float* bhh0 = (const float*)d_in[4];
    const float* Wih1 = (const float*)d_in[5];
    const float* Whh1 = (const float*)d_in[6];
    const float* bih1 = (const float*)d_in[7];
    const float* bhh1 = (const float*)d_in[8];
    const float* fcw  = (const float*)d_in[9];
    const float* fcb  = (const float*)d_in[10];
    float* out = (float*)d_out;

    // floats: sWih 13824 + sh0 8192 + sh1 8192 + sx 576 = 30784 -> 123136 B
    const int gru_smem = (IN0 * G3 + 4 * H * NBP + 2 * IN0 * NBP) * (int)sizeof(float);
    static int smem_set = 0;
    if (!smem_set) {
        cudaFuncSetAttribute(k_gru, cudaFuncAttributeMaxDynamicSharedMemorySize, gru_smem);
        smem_set = 1;
    }

    {
        const size_t total = (size_t)T_STEPS * NBLKK * IN0 * NBR;
        k_xt<<<(int)((total + 255) / 256), 256>>>(x);
    }
    k_transpose<<<G3, 256>>>(Whh0, 0);
    k_transpose<<<G3, 256>>>(Whh1, 1);
    k_transpose<<<G3, 256>>>(Wih1, 2);
    k_gru<<<NBLKK, NTHR, gru_smem>>>(Wih0, bih0, bhh0, bih1, bhh1);
    k_fc<<<BATCH / 8, 256>>>(fcw, fcb, out);
}